// round 2
// baseline (speedup 1.0000x reference)
#include <cuda_runtime.h>
#include <cstdint>

#define T_STEPS 256
#define BATCH   8
#define NPROBES 4
// grid 128x128, source at (64,64) -> warp 8 (rows 64..71), lane 16 (cols 64..67), row j=0, comp .x

__device__ float g_psum[NPROBES];

__global__ void wave_zero_kernel() {
    if (threadIdx.x < NPROBES) g_psum[threadIdx.x] = 0.0f;
}

__global__ __launch_bounds__(512, 1)
void wave_sim_kernel(const float* __restrict__ x,
                     const float* __restrict__ c,
                     const int* __restrict__ probes_i32)
{
    // halo[buf][slot][col]: slot 2w = top row of warp w (row 8w), 2w+1 = bottom row (8w+7)
    __shared__ float halo[2][32][128];
    __shared__ float xsh[T_STEPS];

    const int b   = blockIdx.x;
    const int tid = threadIdx.x;
    const int w   = tid >> 5;      // warp 0..15 : rows 8w..8w+7
    const int l   = tid & 31;      // lane       : cols 4l..4l+3
    const int r0  = w << 3;
    const int c0  = l << 2;

    // preload this batch's source signal
    for (int t = tid; t < T_STEPS; t += 512)
        xsh[t] = x[t * BATCH + b];

    // zero halo buffers (initial fields are zero)
    {
        float4 z = make_float4(0.f, 0.f, 0.f, 0.f);
        float4* hz = reinterpret_cast<float4*>(&halo[0][0][0]);
        for (int i = tid; i < (2 * 32 * 128) / 4; i += 512) hz[i] = z;
    }

    // per-thread state: 8 rows x 4 cols in registers
    float4 kk[8], y1[8], y2[8];
#pragma unroll
    for (int j = 0; j < 8; j++) {
        float4 cv = *reinterpret_cast<const float4*>(&c[(r0 + j) * 128 + c0]);
        kk[j].x = 0.25f * cv.x * cv.x;   // dt^2 * c^2
        kk[j].y = 0.25f * cv.y * cv.y;
        kk[j].z = 0.25f * cv.z * cv.z;
        kk[j].w = 0.25f * cv.w * cv.w;
        y1[j] = make_float4(0.f, 0.f, 0.f, 0.f);
        y2[j] = make_float4(0.f, 0.f, 0.f, 0.f);
    }

    // ---- probe decoding with runtime dtype detection ----
    // Reference does .astype(jnp.int64) but with JAX default x64 DISABLED this
    // is int32 on disk. Detect: values are in [0,128), so if the buffer is
    // int64, every odd int32 word (high halves) is 0. Genuine int32 data has
    // random values in [0,128) at odd words (all-zero prob ~ (1/128)^4).
    int pxv[NPROBES], pyv[NPROBES];
    {
        int odd_or = probes_i32[1] | probes_i32[3] | probes_i32[5] | probes_i32[7];
        if (odd_or == 0) {
            // int64 layout: [px0,0, py0,0, px1,0, py1,0, ...]
#pragma unroll
            for (int p = 0; p < NPROBES; p++) {
                pxv[p] = probes_i32[4 * p];
                pyv[p] = probes_i32[4 * p + 2];
            }
        } else {
            // int32 layout: [px0, py0, px1, py1, ...]
#pragma unroll
            for (int p = 0; p < NPROBES; p++) {
                pxv[p] = probes_i32[2 * p];
                pyv[p] = probes_i32[2 * p + 1];
            }
        }
    }

    float pacc[NPROBES];
    int   pj[NPROBES], pc[NPROBES];
    bool  pmine[NPROBES];
#pragma unroll
    for (int p = 0; p < NPROBES; p++) {
        pacc[p] = 0.f;
        int px = pxv[p];
        int py = pyv[p];
        pmine[p] = (px >= r0) && (px < r0 + 8) && (py >= c0) && (py < c0 + 4);
        pj[p] = px - r0;
        pc[p] = py - c0;
    }

    const bool src_owner = (w == 8) && (l == 16); // (64,64): j=0, component .x

    // constants built exactly as the reference builds them (fp32)
    const float dtb   = 0.5f * 0.005f;            // dt*b
    const float cy2   = -1.0f - dtb;              // -1.0025
    const float denom = 4.0f + (0.5f * 0.005f) / 0.5f;   // 4.005
    const float invd  = 1.0f / denom;

    __syncthreads();

    int cur = 0;
    for (int t = 0; t < T_STEPS; t++) {
        float4 up = make_float4(0.f, 0.f, 0.f, 0.f);
        float4 dn = up;
        if (w > 0)  up = *reinterpret_cast<const float4*>(&halo[cur][((w - 1) << 1) + 1][c0]);
        if (w < 15) dn = *reinterpret_cast<const float4*>(&halo[cur][((w + 1) << 1) + 0][c0]);
        const float xt = xsh[t];

        float4 above = up;   // old value of row j-1
#pragma unroll
        for (int j = 0; j < 8; j++) {
            const float4 v = y1[j];            // old row j
            float4 below = dn;
            if (j < 7) below = y1[j + 1];      // still old (not yet overwritten)

            float lf = __shfl_up_sync(0xffffffffu, v.w, 1);
            float rt = __shfl_down_sync(0xffffffffu, v.x, 1);
            if (l == 0)  lf = 0.f;             // SAME zero padding
            if (l == 31) rt = 0.f;

            float4 nv;
            {
                float lap = (above.x + below.x) + (lf + v.y) - 4.f * v.x;
                nv.x = fmaf(kk[j].x, lap, fmaf(cy2, y2[j].x, 2.0f)) * invd;
            }
            {
                float lap = (above.y + below.y) + (v.x + v.z) - 4.f * v.y;
                nv.y = fmaf(kk[j].y, lap, fmaf(cy2, y2[j].y, 2.0f)) * invd;
            }
            {
                float lap = (above.z + below.z) + (v.y + v.w) - 4.f * v.z;
                nv.z = fmaf(kk[j].z, lap, fmaf(cy2, y2[j].z, 2.0f)) * invd;
            }
            {
                float lap = (above.w + below.w) + (v.z + rt) - 4.f * v.w;
                nv.w = fmaf(kk[j].w, lap, fmaf(cy2, y2[j].w, 2.0f)) * invd;
            }

            // source injection AFTER the update (matches reference .at[].add)
            if (j == 0 && src_owner) nv.x += xt;

            // probe accumulation (post-injection field value)
#pragma unroll
            for (int p = 0; p < NPROBES; p++) {
                if (pmine[p] && pj[p] == j) {
                    float val = (pc[p] == 0) ? nv.x
                              : (pc[p] == 1) ? nv.y
                              : (pc[p] == 2) ? nv.z : nv.w;
                    pacc[p] += val * val;
                }
            }

            y2[j] = v;      // rotate time levels
            y1[j] = nv;
            above = v;      // old row j is next iteration's "above"
        }

        // publish new strip-boundary rows for neighbor warps
        *reinterpret_cast<float4*>(&halo[cur ^ 1][(w << 1) + 0][c0]) = y1[0];
        *reinterpret_cast<float4*>(&halo[cur ^ 1][(w << 1) + 1][c0]) = y1[7];
        __syncthreads();
        cur ^= 1;
    }

#pragma unroll
    for (int p = 0; p < NPROBES; p++)
        if (pmine[p]) atomicAdd(&g_psum[p], pacc[p]);
}

__global__ void wave_fin_kernel(float* __restrict__ out) {
    if (threadIdx.x == 0) {
        float s = g_psum[0] + g_psum[1] + g_psum[2] + g_psum[3];
#pragma unroll
        for (int p = 0; p < NPROBES; p++) out[p] = g_psum[p] / s;
    }
}

extern "C" void kernel_launch(void* const* d_in, const int* in_sizes, int n_in,
                              void* d_out, int out_size)
{
    const float* x      = (const float*)d_in[0];   // (256, 8) f32
    const float* c      = (const float*)d_in[1];   // (128, 128) f32
    const int*   probes = (const int*)d_in[2];     // (4, 2) int32 or int64 — detected in-kernel
    float*       out    = (float*)d_out;           // (4,) f32

    wave_zero_kernel<<<1, 32>>>();
    wave_sim_kernel<<<BATCH, 512>>>(x, c, probes);
    wave_fin_kernel<<<1, 32>>>(out);
}

// round 3
// speedup vs baseline: 1.4276x; 1.4276x over previous
#include <cuda_runtime.h>
#include <cstdint>

#define T_STEPS 256
#define BATCH   8
#define NPROBES 4

typedef unsigned long long ull;

// ---------- f32x2 packed helpers (sm_103a) ----------
__device__ __forceinline__ ull pack2(float lo, float hi) {
    ull r; asm("mov.b64 %0, {%1, %2};" : "=l"(r) : "f"(lo), "f"(hi)); return r;
}
__device__ __forceinline__ void unpack2(ull a, float& lo, float& hi) {
    asm("mov.b64 {%0, %1}, %2;" : "=f"(lo), "=f"(hi) : "l"(a));
}
__device__ __forceinline__ ull add2(ull a, ull b) {
    ull r; asm("add.rn.f32x2 %0, %1, %2;" : "=l"(r) : "l"(a), "l"(b)); return r;
}
__device__ __forceinline__ ull fma2(ull a, ull b, ull c) {
    ull r; asm("fma.rn.f32x2 %0, %1, %2, %3;" : "=l"(r) : "l"(a), "l"(b), "l"(c)); return r;
}

__device__ float g_psum[NPROBES];

__global__ void wave_zero_kernel() {
    if (threadIdx.x < NPROBES) g_psum[threadIdx.x] = 0.0f;
}

// dynamic smem layout (bytes):
//   [0, 65536)        kk2  : ull[128][64]   precomputed 0.25*c^2*invd, packed pairs
//   [65536, 98304)    halo : ull[2][32][64] boundary rows, double-buffered
//   [98304, 99328)    xsh  : float[256]     source signal for this batch
#define SMEM_BYTES 99328

__global__ __launch_bounds__(512, 1)
void wave_sim_kernel(const float* __restrict__ x,
                     const float* __restrict__ c,
                     const int* __restrict__ probes_i32)
{
    extern __shared__ char smem_raw[];
    ull*   kk2  = reinterpret_cast<ull*>(smem_raw);                       // [row*64 + pair]
    ull*   halo = reinterpret_cast<ull*>(smem_raw + 65536);               // [buf*2048 + slot*64 + pair]
    float* xsh  = reinterpret_cast<float*>(smem_raw + 98304);

    const int b   = blockIdx.x;
    const int tid = threadIdx.x;
    const int w   = tid >> 5;      // warp 0..15 : rows 8w..8w+7
    const int l   = tid & 31;      // lane       : cols 4l..4l+3
    const int r0  = w << 3;
    const int c0  = l << 2;

    // constants (reference-exact values, then folded by invd)
    const float dtb   = 0.5f * 0.005f;                 // dt*b
    const float cy2s  = -1.0f - dtb;                   // -1.0025
    const float denom = 4.0f + (0.5f * 0.005f) / 0.5f; // 4.005
    const float invd  = 1.0f / denom;

    const ull NEG4  = pack2(-4.0f, -4.0f);
    const ull CY2P  = pack2(cy2s * invd, cy2s * invd);
    const ull TWO2P = pack2(2.0f * invd, 2.0f * invd);

    // preload this batch's source signal
    for (int t = tid; t < T_STEPS; t += 512)
        xsh[t] = x[t * BATCH + b];

    // zero halo buffers
    for (int i = tid; i < 2 * 32 * 64; i += 512)
        halo[i] = 0ull;

    // fill kk' = 0.25*c^2*invd, packed, into shared; init register state
    ull y1lo[8], y1hi[8], y2lo[8], y2hi[8];
#pragma unroll
    for (int j = 0; j < 8; j++) {
        float4 cv = *reinterpret_cast<const float4*>(&c[(r0 + j) * 128 + c0]);
        kk2[(r0 + j) * 64 + 2 * l]     = pack2(0.25f * cv.x * cv.x * invd,
                                               0.25f * cv.y * cv.y * invd);
        kk2[(r0 + j) * 64 + 2 * l + 1] = pack2(0.25f * cv.z * cv.z * invd,
                                               0.25f * cv.w * cv.w * invd);
        y1lo[j] = 0ull; y1hi[j] = 0ull;
        y2lo[j] = 0ull; y2hi[j] = 0ull;
    }

    // ---- probe decoding (runtime dtype detection: int32 vs int64) ----
    int pxv[NPROBES], pyv[NPROBES];
    {
        int odd_or = probes_i32[1] | probes_i32[3] | probes_i32[5] | probes_i32[7];
        if (odd_or == 0) {
#pragma unroll
            for (int p = 0; p < NPROBES; p++) {
                pxv[p] = probes_i32[4 * p];
                pyv[p] = probes_i32[4 * p + 2];
            }
        } else {
#pragma unroll
            for (int p = 0; p < NPROBES; p++) {
                pxv[p] = probes_i32[2 * p];
                pyv[p] = probes_i32[2 * p + 1];
            }
        }
    }

    float pacc[NPROBES];
    int   pidx[NPROBES];          // 4*j + comp, or -1 if not mine
    bool  pown = false;
#pragma unroll
    for (int p = 0; p < NPROBES; p++) {
        pacc[p] = 0.f;
        int px = pxv[p], py = pyv[p];
        bool mine = (px >= r0) && (px < r0 + 8) && (py >= c0) && (py < c0 + 4);
        pidx[p] = mine ? ((px - r0) * 4 + (py - c0)) : -1;
        pown = pown || mine;
    }

    const bool src_owner = (w == 8) && (l == 16); // (64,64): j=0, low half of lo pair

    __syncthreads();

    int cur = 0;
    for (int t = 0; t < T_STEPS; t++) {
        // read old boundary rows of neighbor warps
        ull up_lo = 0, up_hi = 0, dn_lo = 0, dn_hi = 0;
        if (w > 0) {
            ulonglong2 h = *reinterpret_cast<const ulonglong2*>(
                &halo[cur * 2048 + (2 * (w - 1) + 1) * 64 + 2 * l]);
            up_lo = h.x; up_hi = h.y;
        }
        if (w < 15) {
            ulonglong2 h = *reinterpret_cast<const ulonglong2*>(
                &halo[cur * 2048 + (2 * (w + 1) + 0) * 64 + 2 * l]);
            dn_lo = h.x; dn_hi = h.y;
        }
        const float xt  = src_owner ? xsh[t] : 0.0f;
        const ull   xt2 = pack2(xt, 0.0f);

        ull above_lo = up_lo, above_hi = up_hi;
#pragma unroll
        for (int j = 0; j < 8; j++) {
            const ull v_lo = y1lo[j], v_hi = y1hi[j];
            ull below_lo = dn_lo, below_hi = dn_hi;
            if (j < 7) { below_lo = y1lo[j + 1]; below_hi = y1hi[j + 1]; }

            float vx, vy, vz, vw;
            unpack2(v_lo, vx, vy);
            unpack2(v_hi, vz, vw);

            float lf = __shfl_up_sync(0xffffffffu, vw, 1);
            float rt = __shfl_down_sync(0xffffffffu, vx, 1);
            if (l == 0)  lf = 0.f;
            if (l == 31) rt = 0.f;

            const ull P1 = pack2(lf, vx);
            const ull P2 = pack2(vy, vz);
            const ull P3 = pack2(vw, rt);

            ull lap_lo = add2(add2(above_lo, below_lo), add2(P1, P2));
            lap_lo = fma2(NEG4, v_lo, lap_lo);
            ull lap_hi = add2(add2(above_hi, below_hi), add2(P2, P3));
            lap_hi = fma2(NEG4, v_hi, lap_hi);

            const ulonglong2 kkp = *reinterpret_cast<const ulonglong2*>(
                &kk2[(r0 + j) * 64 + 2 * l]);

            ull nv_lo = fma2(kkp.x, lap_lo, fma2(CY2P, y2lo[j], TWO2P));
            ull nv_hi = fma2(kkp.y, lap_hi, fma2(CY2P, y2hi[j], TWO2P));

            if (j == 0) nv_lo = add2(nv_lo, xt2);   // source injection (xt2==0 for non-owners)

            y2lo[j] = v_lo;  y2hi[j] = v_hi;
            y1lo[j] = nv_lo; y1hi[j] = nv_hi;
            above_lo = v_lo; above_hi = v_hi;
        }

        // probe accumulation: only the <=4 owning threads execute the body
        if (pown) {
#pragma unroll
            for (int p = 0; p < NPROBES; p++) {
                if (pidx[p] >= 0) {
                    float a, bf, val = 0.f;
                    switch (pidx[p]) {
#define GC(J) \
                        case 4*(J)+0: unpack2(y1lo[J], a, bf); val = a;  break; \
                        case 4*(J)+1: unpack2(y1lo[J], a, bf); val = bf; break; \
                        case 4*(J)+2: unpack2(y1hi[J], a, bf); val = a;  break; \
                        case 4*(J)+3: unpack2(y1hi[J], a, bf); val = bf; break;
                        GC(0) GC(1) GC(2) GC(3) GC(4) GC(5) GC(6) GC(7)
#undef GC
                    }
                    pacc[p] += val * val;
                }
            }
        }

        // publish new boundary rows (rows 8w and 8w+7) into the other buffer
        {
            ulonglong2 top; top.x = y1lo[0]; top.y = y1hi[0];
            ulonglong2 bot; bot.x = y1lo[7]; bot.y = y1hi[7];
            *reinterpret_cast<ulonglong2*>(&halo[(cur ^ 1) * 2048 + (2 * w + 0) * 64 + 2 * l]) = top;
            *reinterpret_cast<ulonglong2*>(&halo[(cur ^ 1) * 2048 + (2 * w + 1) * 64 + 2 * l]) = bot;
        }
        __syncthreads();
        cur ^= 1;
    }

#pragma unroll
    for (int p = 0; p < NPROBES; p++)
        if (pidx[p] >= 0) atomicAdd(&g_psum[p], pacc[p]);
}

__global__ void wave_fin_kernel(float* __restrict__ out) {
    if (threadIdx.x == 0) {
        float s = g_psum[0] + g_psum[1] + g_psum[2] + g_psum[3];
#pragma unroll
        for (int p = 0; p < NPROBES; p++) out[p] = g_psum[p] / s;
    }
}

extern "C" void kernel_launch(void* const* d_in, const int* in_sizes, int n_in,
                              void* d_out, int out_size)
{
    const float* x      = (const float*)d_in[0];   // (256, 8) f32
    const float* c      = (const float*)d_in[1];   // (128, 128) f32
    const int*   probes = (const int*)d_in[2];     // (4, 2) int32 (or int64) — detected in-kernel
    float*       out    = (float*)d_out;           // (4,) f32

    cudaFuncSetAttribute(wave_sim_kernel,
                         cudaFuncAttributeMaxDynamicSharedMemorySize, SMEM_BYTES);

    wave_zero_kernel<<<1, 32>>>();
    wave_sim_kernel<<<BATCH, 512, SMEM_BYTES>>>(x, c, probes);
    wave_fin_kernel<<<1, 32>>>(out);
}